// round 15
// baseline (speedup 1.0000x reference)
#include <cuda_runtime.h>
#include <cuda_bf16.h>
#include <cstdint>
#include <math.h>

// ---------------- problem constants ----------------
#define M_TOK 100352            // 2048 * 49 tokens
#define DIM   384
#define NH    12
#define HD    32
#define NT    49
#define NWIN  64
#define RANK  16
#define QKV_N 1152
#define PROJ_N 384
#define SCALE_Q 0.17677669529663687f
#define NKB   (DIM / 8)         // 48 k-blocks of 8
#define NKB16 (DIM / 16)        // 24 k-blocks of 16

// tf32 fragment layouts (m16n8k8):
//  A8'[m>>4][k>>3][lane][4], B8'[n>>3][k>>3][lane][2]
#define A_MB_STRIDE (NKB * 128)   // 6144 floats per 16-row block
#define B_NB_STRIDE (NKB * 64)    // 3072 floats per 8-row block
// bf16 fragment layouts (m16n8k16):
//  A16'[m>>4][k>>4][lane][4 u32], B16'[n>>3][k>>4][lane][2 u32]
#define A16_MB (NKB16 * 256)      // 6144 bf16 per 16-row block
#define B16_NB (NKB16 * 128)      // 3072 bf16 per 8-row block

// Per-(b,h) attention fragment blocks
#define QF_STRIDE 2048
#define KF_STRIDE 1792
#define VF_STRIDE 1792

// ---------------- scratch: device globals ----------------
__device__ float g_Wqkv[QKV_N * DIM];            // main w+res, tf32, B8'
__device__ float g_Wproj[PROJ_N * DIM];
__device__ __nv_bfloat16 g_Wgq[QKV_N * DIM];     // gate weights, bf16, B16'
__device__ __nv_bfloat16 g_Wgp[PROJ_N * DIM];
__device__ float g_bias[NH * NT * NT];
__device__ float g_T[M_TOK * RANK];
__device__ float g_X[M_TOK * DIM];               // tf32-rounded x, A8'
__device__ __nv_bfloat16 g_Xb[M_TOK * DIM];      // bf16 x, A16'
__device__ float g_Qf[24576L * QF_STRIDE];
__device__ float g_Kf[24576L * KF_STRIDE];
__device__ float g_Vf[24576L * VF_STRIDE];
__device__ float g_AO[M_TOK * DIM];              // attn out, A8'
__device__ __nv_bfloat16 g_AOb[M_TOK * DIM];     // attn out, bf16 A16'

// ---------------- helpers ----------------
__device__ __forceinline__ float f2tf_f(float f) {
    uint32_t u;
    asm("cvt.rna.tf32.f32 %0, %1;" : "=r"(u) : "f"(f));
    return __uint_as_float(u);
}
__device__ __forceinline__ void mma_tf32(float* c, const float4& a, float b0, float b1) {
    asm volatile(
        "mma.sync.aligned.m16n8k8.row.col.f32.tf32.tf32.f32 "
        "{%0,%1,%2,%3},{%4,%5,%6,%7},{%8,%9},{%0,%1,%2,%3};"
        : "+f"(c[0]), "+f"(c[1]), "+f"(c[2]), "+f"(c[3])
        : "r"(__float_as_uint(a.x)), "r"(__float_as_uint(a.y)),
          "r"(__float_as_uint(a.z)), "r"(__float_as_uint(a.w)),
          "r"(__float_as_uint(b0)), "r"(__float_as_uint(b1)));
}
__device__ __forceinline__ void mma_bf16(float* c, const uint4& a, uint32_t b0, uint32_t b1) {
    asm volatile(
        "mma.sync.aligned.m16n8k16.row.col.f32.bf16.bf16.f32 "
        "{%0,%1,%2,%3},{%4,%5,%6,%7},{%8,%9},{%0,%1,%2,%3};"
        : "+f"(c[0]), "+f"(c[1]), "+f"(c[2]), "+f"(c[3])
        : "r"(a.x), "r"(a.y), "r"(a.z), "r"(a.w), "r"(b0), "r"(b1));
}
__device__ __forceinline__ void cp16(void* s, const void* g) {
    uint32_t sa = (uint32_t)__cvta_generic_to_shared(s);
    asm volatile("cp.async.cg.shared.global [%0], [%1], 16;" :: "r"(sa), "l"(g));
}
__device__ __forceinline__ void cp_commit() { asm volatile("cp.async.commit_group;"); }
template <int N>
__device__ __forceinline__ void cp_wait() { asm volatile("cp.async.wait_group %0;" :: "n"(N)); }

__device__ __forceinline__ long a_perm_off(long m, int k) {
    return ((m >> 4) * NKB + (k >> 3)) * 128
         + (((int)(m & 7)) * 4 + (k & 3)) * 4
         + ((int)((m >> 3) & 1)) + (((k >> 2) & 1) << 1);
}
__device__ __forceinline__ long b8_off(int n, int k) {
    return (long)((n >> 3) * NKB + (k >> 3)) * 64 + ((n & 7) * 4 + (k & 3)) * 2 + ((k >> 2) & 1);
}
__device__ __forceinline__ long b16_off(int n, int k) {
    return (long)((n >> 3) * NKB16 + (k >> 4)) * 128
         + ((n & 7) * 4 + ((k >> 1) & 3)) * 4 + (((k >> 3) & 1) << 1) + (k & 1);
}

// ---------------- prep ----------------
__global__ void prep_kernel(const float* __restrict__ qkv_w, const float* __restrict__ qkv_res,
                            const float* __restrict__ qkv_gate,
                            const float* __restrict__ proj_w, const float* __restrict__ proj_res,
                            const float* __restrict__ proj_gate,
                            const float* __restrict__ bias_table, const int* __restrict__ rel_index) {
    int stride = gridDim.x * blockDim.x;
    int tid = blockIdx.x * blockDim.x + threadIdx.x;
    for (int e = tid; e < QKV_N * DIM; e += stride) {
        int n = e / DIM, k = e % DIM;
        g_Wqkv[b8_off(n, k)] = f2tf_f(qkv_w[e] + qkv_res[e]);
        g_Wgq[b16_off(n, k)] = __float2bfloat16(qkv_gate[e]);
    }
    for (int e = tid; e < PROJ_N * DIM; e += stride) {
        int n = e / DIM, k = e % DIM;
        g_Wproj[b8_off(n, k)] = f2tf_f(proj_w[e] + proj_res[e]);
        g_Wgp[b16_off(n, k)] = __float2bfloat16(proj_gate[e]);
    }
    for (int e = tid; e < NH * NT * NT; e += stride) {
        int h = e / (NT * NT);
        int ij = e % (NT * NT);
        g_bias[e] = bias_table[rel_index[ij] * NH + h];
    }
}

// ---------------- lora down: T = X @ down^T; PERM=0 also emits A8' + A16' copies ----------------
#define DS4 97
template <int PERM>
__global__ void __launch_bounds__(256) lora_down_kernel(const float* __restrict__ X,
                                                        const float* __restrict__ down,
                                                        float* __restrict__ T,
                                                        float* __restrict__ Xr,
                                                        __nv_bfloat16* __restrict__ Xb) {
    __shared__ __align__(16) float xs[16 * DIM];
    __shared__ __align__(16) float ds[RANK * DS4 * 4];
    long m0 = (long)blockIdx.x * 16;
    int tid = threadIdx.x;
    if (PERM == 0) {
        const float4* Xg = (const float4*)(X + m0 * DIM);
        float4* xs4 = (float4*)xs;
        for (int e = tid; e < 16 * DIM / 4; e += 256) xs4[e] = Xg[e];
    } else {
        const float4* Xg = (const float4*)(X + (m0 >> 4) * A_MB_STRIDE);
        for (int e4 = tid; e4 < 16 * DIM / 4; e4 += 256) {
            int e = e4 * 4;
            int kb = e >> 7;
            int lane = (e & 127) >> 2;
            int ml = lane >> 2;
            int k = kb * 8 + (lane & 3);
            float4 v = Xg[e4];
            xs[ml * DIM + k]           = v.x;
            xs[(ml + 8) * DIM + k]     = v.y;
            xs[ml * DIM + k + 4]       = v.z;
            xs[(ml + 8) * DIM + k + 4] = v.w;
        }
    }
    {
        const float4* dg = (const float4*)down;
        for (int e = tid; e < RANK * DIM / 4; e += 256) {
            int r = e / (DIM / 4), k4 = e % (DIM / 4);
            ((float4*)ds)[r * DS4 + k4] = dg[e];
        }
    }
    __syncthreads();
    if (PERM == 0) {
        float* Xo = Xr + (m0 >> 4) * A_MB_STRIDE;
        for (int e = tid; e < 16 * DIM; e += 256) {
            int kb = e >> 7;
            int rem = e & 127;
            int lane = rem >> 2, inner = rem & 3;
            int ml = (lane >> 2) + ((inner & 1) << 3);
            int k = kb * 8 + (lane & 3) + ((inner >> 1) << 2);
            Xo[e] = f2tf_f(xs[ml * DIM + k]);
        }
        __nv_bfloat16* Xob = Xb + (m0 >> 4) * A16_MB;
        for (int e = tid; e < 16 * DIM; e += 256) {
            int kb16 = e >> 8;
            int rem = e & 255;
            int lane = rem >> 3, r = (rem & 7) >> 1, half = rem & 1;
            int ml = (lane >> 2) + ((r & 1) << 3);
            int k = kb16 * 16 + (lane & 3) * 2 + ((r >> 1) << 3) + half;
            Xob[e] = __float2bfloat16(xs[ml * DIM + k]);
        }
    }
    int ml = tid >> 4;
    int r = tid & 15;
    const float4* xv = (const float4*)(xs + ml * DIM);
    const float4* dv = (const float4*)ds + r * DS4;
    float acc = 0.f;
#pragma unroll 8
    for (int k4 = 0; k4 < DIM / 4; k4++) {
        float4 a = xv[k4], b = dv[k4];
        acc += a.x * b.x + a.y * b.y + a.z * b.z + a.w * b.w;
    }
    T[(m0 + ml) * RANK + r] = acc;
}

// ---------------- GEMM: main tf32 + gate bf16, fragment-permuted, 2-stage pipeline ----------------
// BM=128 x BN=64 real. 8 warps = 4m x 2n, warp 32m x 32n. 2 CTAs/SM.
#define BM 128
#define BN 64
#define BK 32
#define NCH (DIM / BK)          // 12
#define A8_ST 4096
#define B8_ST 2048
#define A16_ST 2048             // u32 units (== floats)
#define B16_ST 1024
#define ST_FL (A8_ST + B8_ST + A16_ST + B16_ST)   // 9216 floats / stage
#define NSTG 2

template <int MODE>  // 0 = qkv scatter to frag layouts, 1 = proj write
__global__ void __launch_bounds__(256, 2) gemm_mma_kernel(
    const float* __restrict__ A8, const __nv_bfloat16* __restrict__ A16,
    const float* __restrict__ B8, const __nv_bfloat16* __restrict__ B16,
    const float* __restrict__ bias, const float* __restrict__ U,
    const float* __restrict__ T, float* __restrict__ outp) {
    extern __shared__ float sm[];
    __shared__ __align__(16) float Ts[BM * RANK];
    __shared__ __align__(16) float Us[BN * RANK];

    int tid = threadIdx.x;
    int warp = tid >> 5, lane = tid & 31;
    int g = lane >> 2, t4 = lane & 3;
    int wm = (warp >> 1) * 32;
    int wn = (warp & 1) * 32;
    int mb_w = (warp >> 1) * 2;
    int nb_w = (warp & 1) * 4;
    int n0 = blockIdx.x * BN;         // n fastest: A reused via L2
    long m0 = (long)blockIdx.y * BM;
    long mb0 = m0 >> 4;
    int nb0 = n0 >> 3;

    float acc[2][4][4], gacc[2][4][4];
#pragma unroll
    for (int i = 0; i < 2; i++)
#pragma unroll
        for (int j = 0; j < 4; j++)
#pragma unroll
            for (int c = 0; c < 4; c++) { acc[i][j][c] = 0.f; gacc[i][j][c] = 0.f; }

    auto load_chunk = [&](int c, int s) {
        float* A8s = sm + s * ST_FL;
        float* B8s = A8s + A8_ST;
        uint32_t* A16s = (uint32_t*)(B8s + B8_ST);
        uint32_t* B16s = A16s + A16_ST;
#pragma unroll
        for (int q = 0; q < 4; q++) {          // A8: 1024 chunks
            int cid = tid + q * 256;
            int mb = cid >> 7, r = cid & 127;
            cp16(&A8s[mb * 512 + r * 4], A8 + (mb0 + mb) * A_MB_STRIDE + c * 512 + r * 4);
        }
#pragma unroll
        for (int q = 0; q < 2; q++) {          // B8: 512 chunks
            int cid = tid + q * 256;
            int nb = cid >> 6, r = cid & 63;
            cp16(&B8s[nb * 256 + r * 4], B8 + (long)(nb0 + nb) * B_NB_STRIDE + c * 256 + r * 4);
        }
#pragma unroll
        for (int q = 0; q < 2; q++) {          // A16: 512 chunks
            int cid = tid + q * 256;
            int mb = cid >> 6, r = cid & 63;
            cp16(&A16s[mb * 256 + r * 4], A16 + (mb0 + mb) * A16_MB + c * 512 + r * 8);
        }
        {                                      // B16: 256 chunks
            int nb = tid >> 5, r = tid & 31;
            cp16(&B16s[nb * 128 + r * 4], B16 + (long)(nb0 + nb) * B16_NB + c * 256 + r * 8);
        }
    };

    load_chunk(0, 0);
    for (int c2 = tid; c2 < 512; c2 += 256)
        cp16(&Ts[c2 * 4], T + m0 * RANK + c2 * 4);
    cp16(&Us[tid * 4], U + (long)n0 * RANK + tid * 4);
    cp_commit();

    for (int c = 0; c < NCH; c++) {
        cp_wait<0>();
        __syncthreads();
        if (c + 1 < NCH) {
            load_chunk(c + 1, (c + 1) & 1);
            cp_commit();
        }
        const float* A8s = sm + (c & 1) * ST_FL;
        const float* B8s = A8s + A8_ST;
        const uint32_t* A16s = (const uint32_t*)(B8s + B8_ST);
        const uint32_t* B16s = A16s + A16_ST;
        // main tf32
#pragma unroll
        for (int ks = 0; ks < 4; ks++) {
            float4 af[2];
            float2 bf[4];
#pragma unroll
            for (int mi = 0; mi < 2; mi++)
                af[mi] = *(const float4*)&A8s[(((mb_w + mi) << 2) + ks) * 128 + lane * 4];
#pragma unroll
            for (int ni = 0; ni < 4; ni++)
                bf[ni] = *(const float2*)&B8s[(((nb_w + ni) << 2) + ks) * 64 + lane * 2];
#pragma unroll
            for (int mi = 0; mi < 2; mi++)
#pragma unroll
                for (int ni = 0; ni < 4; ni++)
                    mma_tf32(acc[mi][ni], af[mi], bf[ni].x, bf[ni].y);
        }
        // gate bf16 (K=16 per mma)
#pragma unroll
        for (int kb16 = 0; kb16 < 2; kb16++) {
            uint4 ga[2];
            uint2 gb[4];
#pragma unroll
            for (int mi = 0; mi < 2; mi++)
                ga[mi] = *(const uint4*)&A16s[(((mb_w + mi) << 1) + kb16) * 128 + lane * 4];
#pragma unroll
            for (int ni = 0; ni < 4; ni++)
                gb[ni] = *(const uint2*)&B16s[(((nb_w + ni) << 1) + kb16) * 64 + lane * 2];
#pragma unroll
            for (int mi = 0; mi < 2; mi++)
#pragma unroll
                for (int ni = 0; ni < 4; ni++)
                    mma_bf16(gacc[mi][ni], ga[mi], gb[ni].x, gb[ni].y);
        }
    }

    // -------- epilogue --------
    float lor[4][8];
#pragma unroll
    for (int i = 0; i < 4; i++)
#pragma unroll
        for (int j = 0; j < 8; j++) lor[i][j] = 0.f;
#pragma unroll
    for (int r = 0; r < RANK; r++) {
        float tv[4], uv[8];
#pragma unroll
        for (int mi = 0; mi < 2; mi++)
#pragma unroll
            for (int rr = 0; rr < 2; rr++)
                tv[mi * 2 + rr] = Ts[(wm + mi * 16 + g + rr * 8) * RANK + r];
#pragma unroll
        for (int ni = 0; ni < 4; ni++) {
            uv[ni * 2 + 0] = Us[(wn + ni * 8 + t4 * 2) * RANK + r];
            uv[ni * 2 + 1] = Us[(wn + ni * 8 + t4 * 2 + 1) * RANK + r];
        }
#pragma unroll
        for (int i = 0; i < 4; i++)
#pragma unroll
            for (int j = 0; j < 8; j++) lor[i][j] += tv[i] * uv[j];
    }

    float2 bv[4];
#pragma unroll
    for (int ni = 0; ni < 4; ni++)
        bv[ni] = *(const float2*)&bias[n0 + wn + ni * 8 + t4 * 2];

#pragma unroll
    for (int mi = 0; mi < 2; mi++) {
#pragma unroll
        for (int rr = 0; rr < 2; rr++) {
            long m = m0 + wm + mi * 16 + g + rr * 8;
            long bb = m / NT;
            int t = (int)(m % NT);
#pragma unroll
            for (int ni = 0; ni < 4; ni++) {
#pragma unroll
                for (int cc = 0; cc < 2; cc++) {
                    int n = n0 + wn + ni * 8 + t4 * 2 + cc;
                    float mainv = acc[mi][ni][rr * 2 + cc];
                    float gatev = gacc[mi][ni][rr * 2 + cc];
                    float gsig = 1.f / (1.f + __expf(-gatev));
                    float bvv = cc ? bv[ni].y : bv[ni].x;
                    float val = mainv + bvv + gsig * 2.0f * lor[mi * 2 + rr][ni * 2 + cc];
                    if (MODE == 0) {
                        int s = n / 384;
                        int rem = n - s * 384;
                        int hh = rem >> 5, d = rem & 31;
                        long bh2 = bb * NH + hh;
                        if (s == 0) {
                            long off = bh2 * QF_STRIDE + (((t >> 4) << 2) + (d >> 3)) * 128
                                     + (((t & 7) << 2) + (d & 3)) * 4 + ((t >> 3) & 1) + (((d >> 2) & 1) << 1);
                            g_Qf[off] = f2tf_f(val * SCALE_Q);
                        } else if (s == 1) {
                            long off = bh2 * KF_STRIDE + (((t >> 3) << 2) + (d >> 3)) * 64
                                     + (((t & 7) << 2) + (d & 3)) * 2 + ((d >> 2) & 1);
                            g_Kf[off] = f2tf_f(val);
                        } else {
                            long off = bh2 * VF_STRIDE + (((t >> 3) << 2) + (d >> 3)) * 64
                                     + (((d & 7) << 2) + (t & 3)) * 2 + ((t >> 2) & 1);
                            g_Vf[off] = f2tf_f(val);
                        }
                    } else {
                        outp[m * DIM + n] = val;
                    }
                }
            }
        }
    }
}

// ---------------- windowed attention (unchanged math; adds bf16 AOb writes) ----------------
#define SPS 58
__global__ void __launch_bounds__(128, 6) attn_kernel(const float* __restrict__ mask,
                                                      float* __restrict__ AO,
                                                      __nv_bfloat16* __restrict__ AOb) {
    __shared__ __align__(16) float qs[QF_STRIDE];
    __shared__ __align__(16) float ks[KF_STRIDE];
    __shared__ __align__(16) float vs[VF_STRIDE];
    __shared__ float sp[64 * SPS];
    __shared__ float rinv[64];
    int bh = blockIdx.x;
    int b = bh / NH, h = bh % NH;
    int wdw = b % NWIN;
    int tid = threadIdx.x;
    int warp = tid >> 5, lane = tid & 31, g = lane >> 2, t4 = lane & 3;

    const float* Qf = g_Qf + (long)bh * QF_STRIDE;
    const float* Kf = g_Kf + (long)bh * KF_STRIDE;
    const float* Vf = g_Vf + (long)bh * VF_STRIDE;
    for (int c = tid; c < QF_STRIDE / 4; c += 128) cp16(&qs[c * 4], Qf + (long)c * 4);
    for (int c = tid; c < KF_STRIDE / 4; c += 128) cp16(&ks[c * 4], Kf + (long)c * 4);
    for (int c = tid; c < VF_STRIDE / 4; c += 128) cp16(&vs[c * 4], Vf + (long)c * 4);
    cp_commit();

    const float* bi = g_bias + h * NT * NT;
    const float* mk = mask + (long)wdw * NT * NT;
    {
        int i = tid / SPS, j = tid % SPS;
        int e = tid;
#pragma unroll 4
        for (int it = 0; it < 64 * SPS / 128; it++) {
            float v = -1e30f;
            if (i < NT && j < NT) {
                int idx = i * NT + j;
                v = bi[idx] + mk[idx];
            }
            sp[e] = v;
            e += 128;
            i += 2; j += 12;
            if (j >= SPS) { j -= SPS; i += 1; }
        }
    }
    cp_wait<0>();
    __syncthreads();

    int base = (warp * 16 + g) * SPS;
    int base2 = base + 8 * SPS;
    float acc[7][4];
#pragma unroll
    for (int nb = 0; nb < 7; nb++) {
        float2 x = *(const float2*)&sp[base + nb * 8 + 2 * t4];
        float2 y = *(const float2*)&sp[base2 + nb * 8 + 2 * t4];
        acc[nb][0] = x.x; acc[nb][1] = x.y; acc[nb][2] = y.x; acc[nb][3] = y.y;
    }
#pragma unroll
    for (int kb = 0; kb < 4; kb++) {
        float4 a = *(const float4*)&qs[(((warp << 2) + kb) * 32 + lane) * 4];
#pragma unroll
        for (int nb = 0; nb < 7; nb++) {
            float2 bv = *(const float2*)&ks[(((nb << 2) + kb) * 32 + lane) * 2];
            mma_tf32(acc[nb], a, bv.x, bv.y);
        }
    }

    float mx1 = -1e30f, mx2 = -1e30f;
#pragma unroll
    for (int nb = 0; nb < 7; nb++) {
        mx1 = fmaxf(mx1, fmaxf(acc[nb][0], acc[nb][1]));
        mx2 = fmaxf(mx2, fmaxf(acc[nb][2], acc[nb][3]));
    }
    mx1 = fmaxf(mx1, __shfl_xor_sync(0xffffffffu, mx1, 1));
    mx1 = fmaxf(mx1, __shfl_xor_sync(0xffffffffu, mx1, 2));
    mx2 = fmaxf(mx2, __shfl_xor_sync(0xffffffffu, mx2, 1));
    mx2 = fmaxf(mx2, __shfl_xor_sync(0xffffffffu, mx2, 2));
    float s1 = 0.f, s2 = 0.f;
#pragma unroll
    for (int nb = 0; nb < 7; nb++) {
        acc[nb][0] = __expf(acc[nb][0] - mx1);
        acc[nb][1] = __expf(acc[nb][1] - mx1);
        acc[nb][2] = __expf(acc[nb][2] - mx2);
        acc[nb][3] = __expf(acc[nb][3] - mx2);
        s1 += acc[nb][0] + acc[nb][1];
        s2 += acc[nb][2] + acc[nb][3];
    }
    s1 += __shfl_xor_sync(0xffffffffu, s1, 1);
    s1 += __shfl_xor_sync(0xffffffffu, s1, 2);
    s2 += __shfl_xor_sync(0xffffffffu, s2, 1);
    s2 += __shfl_xor_sync(0xffffffffu, s2, 2);
    if (t4 == 0) {
        rinv[warp * 16 + g] = 1.f / s1;
        rinv[warp * 16 + 8 + g] = 1.f / s2;
    }
#pragma unroll
    for (int nb = 0; nb < 7; nb++) {
        *(float2*)&sp[base + nb * 8 + 2 * t4]  = make_float2(f2tf_f(acc[nb][0]), f2tf_f(acc[nb][1]));
        *(float2*)&sp[base2 + nb * 8 + 2 * t4] = make_float2(f2tf_f(acc[nb][2]), f2tf_f(acc[nb][3]));
    }
    __syncwarp();

    float acc2[4][4];
#pragma unroll
    for (int i = 0; i < 4; i++)
#pragma unroll
        for (int j = 0; j < 4; j++) acc2[i][j] = 0.f;
#pragma unroll
    for (int kb2 = 0; kb2 < 7; kb2++) {
        float4 a;
        a.x = sp[base + kb2 * 8 + t4];
        a.y = sp[base2 + kb2 * 8 + t4];
        a.z = sp[base + kb2 * 8 + t4 + 4];
        a.w = sp[base2 + kb2 * 8 + t4 + 4];
#pragma unroll
        for (int nb = 0; nb < 4; nb++) {
            float2 bv = *(const float2*)&vs[(((kb2 << 2) + nb) * 32 + lane) * 2];
            mma_tf32(acc2[nb], a, bv.x, bv.y);
        }
    }

    int i1 = warp * 16 + g, i2 = i1 + 8;
    float ri1 = rinv[i1], ri2 = rinv[i2];
    long m1 = (long)b * NT + i1, m2 = (long)b * NT + i2;
#pragma unroll
    for (int nb = 0; nb < 4; nb++) {
        int d0 = nb * 8 + 2 * t4;
        int k = h * HD + d0;
        if (i1 < NT) {
            float v0 = acc2[nb][0] * ri1, v1 = acc2[nb][1] * ri1;
            long off = a_perm_off(m1, k);
            AO[off]     = f2tf_f(v0);
            AO[off + 4] = f2tf_f(v1);
            int lane16 = ((int)(m1 & 7)) * 4 + t4;
            int r16 = ((int)((m1 >> 3) & 1)) + ((nb & 1) << 1);
            long ob = ((m1 >> 4) * NKB16 + (k >> 4)) * 256 + lane16 * 8 + r16 * 2;
            *(__nv_bfloat162*)&AOb[ob] = __nv_bfloat162(__float2bfloat16(v0), __float2bfloat16(v1));
        }
        if (i2 < NT) {
            float v0 = acc2[nb][2] * ri2, v1 = acc2[nb][3] * ri2;
            long off = a_perm_off(m2, k);
            AO[off]     = f2tf_f(v0);
            AO[off + 4] = f2tf_f(v1);
            int lane16 = ((int)(m2 & 7)) * 4 + t4;
            int r16 = ((int)((m2 >> 3) & 1)) + ((nb & 1) << 1);
            long ob = ((m2 >> 4) * NKB16 + (k >> 4)) * 256 + lane16 * 8 + r16 * 2;
            *(__nv_bfloat162*)&AOb[ob] = __nv_bfloat162(__float2bfloat16(v0), __float2bfloat16(v1));
        }
    }
}

// ---------------- launch ----------------
extern "C" void kernel_launch(void* const* d_in, const int* in_sizes, int n_in,
                              void* d_out, int out_size) {
    const float* x          = (const float*)d_in[0];
    const float* mask       = (const float*)d_in[1];
    const float* qkv_w      = (const float*)d_in[2];
    const float* qkv_b      = (const float*)d_in[3];
    const float* qkv_down   = (const float*)d_in[4];
    const float* qkv_up     = (const float*)d_in[5];
    const float* qkv_gate   = (const float*)d_in[6];
    const float* qkv_res    = (const float*)d_in[7];
    const float* proj_w     = (const float*)d_in[8];
    const float* proj_b     = (const float*)d_in[9];
    const float* proj_down  = (const float*)d_in[10];
    const float* proj_up    = (const float*)d_in[11];
    const float* proj_gate  = (const float*)d_in[12];
    const float* proj_res   = (const float*)d_in[13];
    const float* bias_table = (const float*)d_in[14];
    const int*   rel_index  = (const int*)d_in[15];
    float* out = (float*)d_out;

    float *pT, *pX, *pAO, *pWq, *pWp;
    __nv_bfloat16 *pXb, *pAOb, *pWgq, *pWgp;
    cudaGetSymbolAddress((void**)&pT, g_T);
    cudaGetSymbolAddress((void**)&pX, g_X);
    cudaGetSymbolAddress((void**)&pAO, g_AO);
    cudaGetSymbolAddress((void**)&pWq, g_Wqkv);
    cudaGetSymbolAddress((void**)&pWp, g_Wproj);
    cudaGetSymbolAddress((void**)&pXb, g_Xb);
    cudaGetSymbolAddress((void**)&pAOb, g_AOb);
    cudaGetSymbolAddress((void**)&pWgq, g_Wgq);
    cudaGetSymbolAddress((void**)&pWgp, g_Wgp);

    int smem = NSTG * ST_FL * sizeof(float);   // 73728 bytes dynamic (+12KB static)
    cudaFuncSetAttribute(gemm_mma_kernel<0>, cudaFuncAttributeMaxDynamicSharedMemorySize, smem);
    cudaFuncSetAttribute(gemm_mma_kernel<1>, cudaFuncAttributeMaxDynamicSharedMemorySize, smem);

    prep_kernel<<<1024, 256>>>(qkv_w, qkv_res, qkv_gate, proj_w, proj_res, proj_gate,
                               bias_table, rel_index);
    lora_down_kernel<0><<<M_TOK / 16, 256>>>(x, qkv_down, pT, pX, pXb);
    dim3 gq(QKV_N / BN, M_TOK / BM);   // (18, 784)
    gemm_mma_kernel<0><<<gq, 256, smem>>>(pX, pXb, pWq, pWgq, qkv_b, qkv_up, pT, nullptr);
    attn_kernel<<<2048 * NH, 128>>>(mask, pAO, pAOb);
    lora_down_kernel<1><<<M_TOK / 16, 256>>>(pAO, proj_down, pT, nullptr, nullptr);
    dim3 gp(PROJ_N / BN, M_TOK / BM);  // (6, 784)
    gemm_mma_kernel<1><<<gp, 256, smem>>>(pAO, pAOb, pWp, pWgp, proj_b, proj_up, pT, out);
}

// round 16
// speedup vs baseline: 1.0302x; 1.0302x over previous
#include <cuda_runtime.h>
#include <cstdint>
#include <math.h>

// ---------------- problem constants ----------------
#define M_TOK 100352            // 2048 * 49 tokens
#define DIM   384
#define NH    12
#define HD    32
#define NT    49
#define NWIN  64
#define RANK  16
#define QKV_NPACK 2304          // interleaved (main,gate) rows
#define PROJ_NPACK 768
#define SCALE_Q 0.17677669529663687f
#define NKB   (DIM / 8)         // 48 k-blocks of 8

// Fragment-permuted global layouts:
//  A'[m>>4][k>>3][lane][4] : lane=(m&7)*4+(k&3), inner=(m>>3&1)+2*((k>>2)&1)
//  B'[n>>3][k>>3][lane][2] : lane=(n&7)*4+(k&3), inner=(k>>2)&1
#define A_MB_STRIDE (NKB * 128)   // 6144 floats per 16-row block
#define B_NB_STRIDE (NKB * 64)    // 3072 floats per 8-row block

// Per-(b,h) attention fragment blocks (padding rows stay zero: never written)
#define QF_STRIDE 2048            // [4 mb][4 kb][32 lane][4]
#define KF_STRIDE 1792            // [7 nb][4 kb][32 lane][2]
#define VF_STRIDE 1792            // [7 kb2][4 nb][32 lane][2]

// ---------------- scratch: device globals ----------------
__device__ float g_Wqkv[QKV_NPACK * DIM];   // B'-permuted packed weights
__device__ float g_Wproj[PROJ_NPACK * DIM];
__device__ float g_bias[NH * NT * NT];
__device__ float g_T[M_TOK * RANK];
__device__ float g_X[M_TOK * DIM];          // A'-permuted tf32-rounded x
__device__ float g_Qf[24576L * QF_STRIDE];  // Q in attn A-frag layout (pre-scaled)
__device__ float g_Kf[24576L * KF_STRIDE];  // K in attn B-frag layout
__device__ float g_Vf[24576L * VF_STRIDE];  // V in attn PV B-frag layout
__device__ float g_AO[M_TOK * DIM];         // A'-permuted tf32-rounded attn output

// ---------------- helpers ----------------
__device__ __forceinline__ float f2tf_f(float f) {
    uint32_t u;
    asm("cvt.rna.tf32.f32 %0, %1;" : "=r"(u) : "f"(f));
    return __uint_as_float(u);
}
__device__ __forceinline__ void mma_tf32(float* c, const float4& a, float b0, float b1) {
    asm volatile(
        "mma.sync.aligned.m16n8k8.row.col.f32.tf32.tf32.f32 "
        "{%0,%1,%2,%3},{%4,%5,%6,%7},{%8,%9},{%0,%1,%2,%3};"
        : "+f"(c[0]), "+f"(c[1]), "+f"(c[2]), "+f"(c[3])
        : "r"(__float_as_uint(a.x)), "r"(__float_as_uint(a.y)),
          "r"(__float_as_uint(a.z)), "r"(__float_as_uint(a.w)),
          "r"(__float_as_uint(b0)), "r"(__float_as_uint(b1)));
}
__device__ __forceinline__ void cp16(void* s, const void* g) {
    uint32_t sa = (uint32_t)__cvta_generic_to_shared(s);
    asm volatile("cp.async.cg.shared.global [%0], [%1], 16;" :: "r"(sa), "l"(g));
}
__device__ __forceinline__ void cp_commit() { asm volatile("cp.async.commit_group;"); }
template <int N>
__device__ __forceinline__ void cp_wait() { asm volatile("cp.async.wait_group %0;" :: "n"(N)); }

__device__ __forceinline__ long a_perm_off(long m, int k) {
    return ((m >> 4) * NKB + (k >> 3)) * 128
         + (((int)(m & 7)) * 4 + (k & 3)) * 4
         + ((int)((m >> 3) & 1)) + (((k >> 2) & 1) << 1);
}

// ---------------- prep ----------------
__global__ void prep_kernel(const float* __restrict__ qkv_w, const float* __restrict__ qkv_res,
                            const float* __restrict__ qkv_gate,
                            const float* __restrict__ proj_w, const float* __restrict__ proj_res,
                            const float* __restrict__ proj_gate,
                            const float* __restrict__ bias_table, const int* __restrict__ rel_index) {
    int stride = gridDim.x * blockDim.x;
    int tid = blockIdx.x * blockDim.x + threadIdx.x;
    auto boff = [](int np, int k) {
        return (long)((np >> 3) * NKB + (k >> 3)) * 64 + ((np & 7) * 4 + (k & 3)) * 2 + ((k >> 2) & 1);
    };
    for (int e = tid; e < (QKV_NPACK / 2) * DIM; e += stride) {
        int n = e / DIM, k = e % DIM;
        g_Wqkv[boff(2 * n, k)]     = f2tf_f(qkv_w[e] + qkv_res[e]);
        g_Wqkv[boff(2 * n + 1, k)] = f2tf_f(qkv_gate[e]);
    }
    for (int e = tid; e < (PROJ_NPACK / 2) * DIM; e += stride) {
        int n = e / DIM, k = e % DIM;
        g_Wproj[boff(2 * n, k)]     = f2tf_f(proj_w[e] + proj_res[e]);
        g_Wproj[boff(2 * n + 1, k)] = f2tf_f(proj_gate[e]);
    }
    for (int e = tid; e < NH * NT * NT; e += stride) {
        int h = e / (NT * NT);
        int ij = e % (NT * NT);
        g_bias[e] = bias_table[rel_index[ij] * NH + h];
    }
}

// ---------------- lora down: T = X @ down^T (fp32), float4 paths ----------------
// PERM=0: X row-linear (+ writes permuted tf32 copy to Xr). PERM=1: X A'-permuted.
#define DS4 97     // float4 row stride for staged down (388 floats)
template <int PERM>
__global__ void __launch_bounds__(256) lora_down_kernel(const float* __restrict__ X,
                                                        const float* __restrict__ down,
                                                        float* __restrict__ T,
                                                        float* __restrict__ Xr) {
    __shared__ __align__(16) float xs[16 * DIM];
    __shared__ __align__(16) float ds[RANK * DS4 * 4];
    long m0 = (long)blockIdx.x * 16;
    int tid = threadIdx.x;
    if (PERM == 0) {
        const float4* Xb = (const float4*)(X + m0 * DIM);
        float4* xs4 = (float4*)xs;
        for (int e = tid; e < 16 * DIM / 4; e += 256) xs4[e] = Xb[e];
    } else {
        const float4* Xb = (const float4*)(X + (m0 >> 4) * A_MB_STRIDE);
        for (int e4 = tid; e4 < 16 * DIM / 4; e4 += 256) {
            int e = e4 * 4;
            int kb = e >> 7;
            int lane = (e & 127) >> 2;
            int ml = lane >> 2;
            int k = kb * 8 + (lane & 3);
            float4 v = Xb[e4];
            xs[ml * DIM + k]             = v.x;
            xs[(ml + 8) * DIM + k]       = v.y;
            xs[ml * DIM + k + 4]         = v.z;
            xs[(ml + 8) * DIM + k + 4]   = v.w;
        }
    }
    {
        const float4* dg = (const float4*)down;
        for (int e = tid; e < RANK * DIM / 4; e += 256) {
            int r = e / (DIM / 4), k4 = e % (DIM / 4);
            ((float4*)ds)[r * DS4 + k4] = dg[e];
        }
    }
    __syncthreads();
    if (PERM == 0 && Xr) {
        float* Xb = Xr + (m0 >> 4) * A_MB_STRIDE;
        for (int e = tid; e < 16 * DIM; e += 256) {
            int kb = e >> 7;
            int rem = e & 127;
            int lane = rem >> 2, inner = rem & 3;
            int ml = (lane >> 2) + ((inner & 1) << 3);
            int k = kb * 8 + (lane & 3) + ((inner >> 1) << 2);
            Xb[e] = f2tf_f(xs[ml * DIM + k]);
        }
    }
    int ml = tid >> 4;
    int r = tid & 15;
    const float4* xv = (const float4*)(xs + ml * DIM);
    const float4* dv = (const float4*)ds + r * DS4;
    float acc = 0.f;
#pragma unroll 8
    for (int k4 = 0; k4 < DIM / 4; k4++) {
        float4 a = xv[k4], b = dv[k4];
        acc += a.x * b.x + a.y * b.y + a.z * b.z + a.w * b.w;
    }
    T[(m0 + ml) * RANK + r] = acc;
}

// ---------------- tf32 mma.sync GEMM, fragment-permuted operands, 3-stage pipeline ----------------
// BM=128 x BNP=128, 8 warps as 2m x 4n, warp tile 64m x 32np, 2 CTAs/SM.
#define BM 128
#define BNP 128                 // packed columns (64 real outputs)
#define BK 32
#define NCH (DIM / BK)          // 12
#define A_ST (BM * BK)          // 4096 floats / stage
#define B_ST (BNP * BK)         // 4096 floats / stage
#define ST_FL (A_ST + B_ST)     // 8192 floats / stage
#define NSTG 3

template <int MODE>  // 0 = qkv scatter to frag layouts, 1 = proj write
__global__ void __launch_bounds__(256, 2) gemm_mma_kernel(
    const float* __restrict__ A, const float* __restrict__ Bp,
    const float* __restrict__ bias, const float* __restrict__ U,
    const float* __restrict__ T, float* __restrict__ outp) {
    extern __shared__ float sm[];
    __shared__ __align__(16) float Ts[BM * RANK];   // stride 16 (64B rows): cp.async-aligned
    __shared__ __align__(16) float Us[64 * RANK];

    int tid = threadIdx.x;
    int warp = tid >> 5, lane = tid & 31;
    int g = lane >> 2, t4 = lane & 3;
    int warp_m = warp >> 2;           // 0..1, 64-row stripes
    int warp_n = warp & 3;            // 0..3, 32-packed stripes
    int wm = warp_m * 64;
    int wn = warp_n * 32;
    int mb_w = warp_m * 4;            // 4 A 16-row blocks per warp
    int nb_w = warp_n * 4;            // 4 B 8-row blocks per warp
    int n0p = blockIdx.x * BNP;       // n FASTEST in grid: A reused via L2
    long m0 = (long)blockIdx.y * BM;
    long mb0 = m0 >> 4;
    int nb0 = n0p >> 3;
    int n0r = n0p >> 1;

    float acc[4][4][4];
#pragma unroll
    for (int i = 0; i < 4; i++)
#pragma unroll
        for (int j = 0; j < 4; j++)
#pragma unroll
            for (int c = 0; c < 4; c++) acc[i][j][c] = 0.f;

    auto load_chunk = [&](int c, int s) {
        float* As = sm + s * ST_FL;
        float* Bs = As + A_ST;
        const float* Agc = A + mb0 * A_MB_STRIDE + c * 512;   // 4 kb * 128 floats per mb
        const float* Bgc = Bp + (long)nb0 * B_NB_STRIDE + c * 256;
#pragma unroll
        for (int q = 0; q < 4; q++) {          // A: 1024 16B chunks (8 mb-runs of 2KB)
            int cid = tid + q * 256;
            int mb = cid >> 7, r = cid & 127;
            cp16(&As[mb * 512 + r * 4], Agc + (long)mb * A_MB_STRIDE + r * 4);
        }
#pragma unroll
        for (int q = 0; q < 4; q++) {          // B: 1024 16B chunks (16 nb-runs of 1KB)
            int cid = tid + q * 256;
            int nb = cid >> 6, r = cid & 63;
            cp16(&Bs[nb * 256 + r * 4], Bgc + (long)nb * B_NB_STRIDE + r * 4);
        }
    };

    // prefetch Ts/Us bundled with the first chunk's group (ready by first cp_wait + barrier)
    load_chunk(0, 0);
    {
        for (int c2 = tid; c2 < 512; c2 += 256)
            cp16(&Ts[c2 * 4], T + m0 * RANK + c2 * 4);
        cp16(&Us[tid * 4], U + (long)n0r * RANK + tid * 4);
    }
    cp_commit();
    load_chunk(1, 1); cp_commit();
    for (int c = 0; c < NCH; c++) {
        if (c < NCH - 1) cp_wait<1>();
        else cp_wait<0>();
        __syncthreads();
        if (c + 2 < NCH) {
            load_chunk(c + 2, (c + 2) % NSTG);
            cp_commit();
        }
        const float* Ab = sm + (c % NSTG) * ST_FL;
        const float* Bb = Ab + A_ST;
#pragma unroll
        for (int ks = 0; ks < 4; ks++) {
            float4 af[4];
            float2 bf[4];
#pragma unroll
            for (int mi = 0; mi < 4; mi++)
                af[mi] = *(const float4*)&Ab[(((mb_w + mi) << 2) + ks) * 128 + lane * 4];
#pragma unroll
            for (int ni = 0; ni < 4; ni++)
                bf[ni] = *(const float2*)&Bb[(((nb_w + ni) << 2) + ks) * 64 + lane * 2];
#pragma unroll
            for (int mi = 0; mi < 4; mi++)
#pragma unroll
                for (int ni = 0; ni < 4; ni++)
                    mma_tf32(acc[mi][ni], af[mi], bf[ni].x, bf[ni].y);
        }
    }

    // -------- epilogue: lora + bias + sigmoid gate, scatter (Ts/Us already staged) --------
    float lor[8][4];
#pragma unroll
    for (int i = 0; i < 8; i++)
#pragma unroll
        for (int j = 0; j < 4; j++) lor[i][j] = 0.f;
#pragma unroll
    for (int r = 0; r < RANK; r++) {
        float tv[8], uv[4];
#pragma unroll
        for (int mi = 0; mi < 4; mi++)
#pragma unroll
            for (int rr = 0; rr < 2; rr++)
                tv[mi * 2 + rr] = Ts[(wm + mi * 16 + g + rr * 8) * RANK + r];
#pragma unroll
        for (int ni = 0; ni < 4; ni++)
            uv[ni] = Us[((wn >> 1) + ni * 4 + t4) * RANK + r];
#pragma unroll
        for (int i = 0; i < 8; i++)
#pragma unroll
            for (int j = 0; j < 4; j++) lor[i][j] += tv[i] * uv[j];
    }

    float bv[4];
#pragma unroll
    for (int ni = 0; ni < 4; ni++) bv[ni] = __ldg(&bias[n0r + (wn >> 1) + ni * 4 + t4]);

#pragma unroll
    for (int mi = 0; mi < 4; mi++) {
#pragma unroll
        for (int rr = 0; rr < 2; rr++) {
            long m = m0 + wm + mi * 16 + g + rr * 8;
            unsigned um = (unsigned)m;          // m < 2^31: u32 magic-mul division
            unsigned ubb = um / NT;
            int t = (int)(um - ubb * NT);
            long bb = (long)ubb;
#pragma unroll
            for (int ni = 0; ni < 4; ni++) {
                int n = n0r + (wn >> 1) + ni * 4 + t4;
                float mainv = acc[mi][ni][rr * 2 + 0];
                float gatev = acc[mi][ni][rr * 2 + 1];
                float gsig = 1.f / (1.f + __expf(-gatev));
                float val = mainv + bv[ni] + gsig * 2.0f * lor[mi * 2 + rr][ni];
                if (MODE == 0) {
                    int s = n / 384;
                    int rem = n - s * 384;
                    int hh = rem >> 5, d = rem & 31;
                    long bh2 = bb * NH + hh;
                    if (s == 0) {
                        long off = bh2 * QF_STRIDE + (((t >> 4) << 2) + (d >> 3)) * 128
                                 + (((t & 7) << 2) + (d & 3)) * 4 + ((t >> 3) & 1) + (((d >> 2) & 1) << 1);
                        g_Qf[off] = f2tf_f(val * SCALE_Q);
                    } else if (s == 1) {
                        long off = bh2 * KF_STRIDE + (((t >> 3) << 2) + (d >> 3)) * 64
                                 + (((t & 7) << 2) + (d & 3)) * 2 + ((d >> 2) & 1);
                        g_Kf[off] = f2tf_f(val);
                    } else {
                        long off = bh2 * VF_STRIDE + (((t >> 3) << 2) + (d >> 3)) * 64
                                 + (((d & 7) << 2) + (t & 3)) * 2 + ((t >> 2) & 1);
                        g_Vf[off] = f2tf_f(val);
                    }
                } else {
                    outp[m * DIM + n] = val;
                }
            }
        }
    }
}

// ---------------- windowed attention, tensor-core, pre-fragmented operands ----------------
#define SPS 58
__global__ void __launch_bounds__(128, 6) attn_kernel(const float* __restrict__ mask,
                                                      float* __restrict__ AO) {
    __shared__ __align__(16) float qs[QF_STRIDE];
    __shared__ __align__(16) float ks[KF_STRIDE];
    __shared__ __align__(16) float vs[VF_STRIDE];
    __shared__ float sp[64 * SPS];
    __shared__ float rinv[64];
    int bh = blockIdx.x;
    int b = bh / NH, h = bh % NH;
    int wdw = b % NWIN;
    int tid = threadIdx.x;
    int warp = tid >> 5, lane = tid & 31, g = lane >> 2, t4 = lane & 3;

    const float* Qf = g_Qf + (long)bh * QF_STRIDE;
    const float* Kf = g_Kf + (long)bh * KF_STRIDE;
    const float* Vf = g_Vf + (long)bh * VF_STRIDE;
    for (int c = tid; c < QF_STRIDE / 4; c += 128) cp16(&qs[c * 4], Qf + (long)c * 4);
    for (int c = tid; c < KF_STRIDE / 4; c += 128) cp16(&ks[c * 4], Kf + (long)c * 4);
    for (int c = tid; c < VF_STRIDE / 4; c += 128) cp16(&vs[c * 4], Vf + (long)c * 4);
    cp_commit();

    // score board fill with incremental (i, j) tracking: no divides in loop
    const float* bi = g_bias + h * NT * NT;
    const float* mk = mask + (long)wdw * NT * NT;
    {
        int i = tid / SPS, j = tid % SPS;
        int e = tid;
#pragma unroll 4
        for (int it = 0; it < 64 * SPS / 128; it++) {
            float v = -1e30f;
            if (i < NT && j < NT) {
                int idx = i * NT + j;
                v = bi[idx] + mk[idx];
            }
            sp[e] = v;
            e += 128;
            i += 2; j += 12;
            if (j >= SPS) { j -= SPS; i += 1; }
        }
    }
    cp_wait<0>();
    __syncthreads();

    int base = (warp * 16 + g) * SPS;
    int base2 = base + 8 * SPS;
    float acc[7][4];
#pragma unroll
    for (int nb = 0; nb < 7; nb++) {
        float2 x = *(const float2*)&sp[base + nb * 8 + 2 * t4];
        float2 y = *(const float2*)&sp[base2 + nb * 8 + 2 * t4];
        acc[nb][0] = x.x; acc[nb][1] = x.y; acc[nb][2] = y.x; acc[nb][3] = y.y;
    }
#pragma unroll
    for (int kb = 0; kb < 4; kb++) {
        float4 a = *(const float4*)&qs[(((warp << 2) + kb) * 32 + lane) * 4];
#pragma unroll
        for (int nb = 0; nb < 7; nb++) {
            float2 bv = *(const float2*)&ks[(((nb << 2) + kb) * 32 + lane) * 2];
            mma_tf32(acc[nb], a, bv.x, bv.y);
        }
    }

    float mx1 = -1e30f, mx2 = -1e30f;
#pragma unroll
    for (int nb = 0; nb < 7; nb++) {
        mx1 = fmaxf(mx1, fmaxf(acc[nb][0], acc[nb][1]));
        mx2 = fmaxf(mx2, fmaxf(acc[nb][2], acc[nb][3]));
    }
    mx1 = fmaxf(mx1, __shfl_xor_sync(0xffffffffu, mx1, 1));
    mx1 = fmaxf(mx1, __shfl_xor_sync(0xffffffffu, mx1, 2));
    mx2 = fmaxf(mx2, __shfl_xor_sync(0xffffffffu, mx2, 1));
    mx2 = fmaxf(mx2, __shfl_xor_sync(0xffffffffu, mx2, 2));
    float s1 = 0.f, s2 = 0.f;
#pragma unroll
    for (int nb = 0; nb < 7; nb++) {
        acc[nb][0] = __expf(acc[nb][0] - mx1);
        acc[nb][1] = __expf(acc[nb][1] - mx1);
        acc[nb][2] = __expf(acc[nb][2] - mx2);
        acc[nb][3] = __expf(acc[nb][3] - mx2);
        s1 += acc[nb][0] + acc[nb][1];
        s2 += acc[nb][2] + acc[nb][3];
    }
    s1 += __shfl_xor_sync(0xffffffffu, s1, 1);
    s1 += __shfl_xor_sync(0xffffffffu, s1, 2);
    s2 += __shfl_xor_sync(0xffffffffu, s2, 1);
    s2 += __shfl_xor_sync(0xffffffffu, s2, 2);
    if (t4 == 0) {
        rinv[warp * 16 + g] = 1.f / s1;
        rinv[warp * 16 + 8 + g] = 1.f / s2;
    }
#pragma unroll
    for (int nb = 0; nb < 7; nb++) {
        *(float2*)&sp[base + nb * 8 + 2 * t4]  = make_float2(f2tf_f(acc[nb][0]), f2tf_f(acc[nb][1]));
        *(float2*)&sp[base2 + nb * 8 + 2 * t4] = make_float2(f2tf_f(acc[nb][2]), f2tf_f(acc[nb][3]));
    }
    __syncwarp();

    float acc2[4][4];
#pragma unroll
    for (int i = 0; i < 4; i++)
#pragma unroll
        for (int j = 0; j < 4; j++) acc2[i][j] = 0.f;
#pragma unroll
    for (int kb2 = 0; kb2 < 7; kb2++) {
        float4 a;
        a.x = sp[base + kb2 * 8 + t4];
        a.y = sp[base2 + kb2 * 8 + t4];
        a.z = sp[base + kb2 * 8 + t4 + 4];
        a.w = sp[base2 + kb2 * 8 + t4 + 4];
#pragma unroll
        for (int nb = 0; nb < 4; nb++) {
            float2 bv = *(const float2*)&vs[(((kb2 << 2) + nb) * 32 + lane) * 2];
            mma_tf32(acc2[nb], a, bv.x, bv.y);
        }
    }

    // epilogue: one a_perm_off per row, +128 per nb (k>>3 advances by 1)
    int i1 = warp * 16 + g, i2 = i1 + 8;
    float ri1 = rinv[i1], ri2 = rinv[i2];
    long m1 = (long)b * NT + i1, m2 = (long)b * NT + i2;
    long off1 = a_perm_off(m1, h * HD + 2 * t4);
    long off2 = a_perm_off(m2, h * HD + 2 * t4);
#pragma unroll
    for (int nb = 0; nb < 4; nb++) {
        if (i1 < NT) {
            AO[off1]     = f2tf_f(acc2[nb][0] * ri1);
            AO[off1 + 4] = f2tf_f(acc2[nb][1] * ri1);
        }
        if (i2 < NT) {
            AO[off2]     = f2tf_f(acc2[nb][2] * ri2);
            AO[off2 + 4] = f2tf_f(acc2[nb][3] * ri2);
        }
        off1 += 128;
        off2 += 128;
    }
}

// ---------------- launch ----------------
extern "C" void kernel_launch(void* const* d_in, const int* in_sizes, int n_in,
                              void* d_out, int out_size) {
    const float* x          = (const float*)d_in[0];
    const float* mask       = (const float*)d_in[1];
    const float* qkv_w      = (const float*)d_in[2];
    const float* qkv_b      = (const float*)d_in[3];
    const float* qkv_down   = (const float*)d_in[4];
    const float* qkv_up     = (const float*)d_in[5];
    const float* qkv_gate   = (const float*)d_in[6];
    const float* qkv_res    = (const float*)d_in[7];
    const float* proj_w     = (const float*)d_in[8];
    const float* proj_b     = (const float*)d_in[9];
    const float* proj_down  = (const float*)d_in[10];
    const float* proj_up    = (const float*)d_in[11];
    const float* proj_gate  = (const float*)d_in[12];
    const float* proj_res   = (const float*)d_in[13];
    const float* bias_table = (const float*)d_in[14];
    const int*   rel_index  = (const int*)d_in[15];
    float* out = (float*)d_out;

    float *pT, *pX, *pAO, *pWq, *pWp;
    cudaGetSymbolAddress((void**)&pT, g_T);
    cudaGetSymbolAddress((void**)&pX, g_X);
    cudaGetSymbolAddress((void**)&pAO, g_AO);
    cudaGetSymbolAddress((void**)&pWq, g_Wqkv);
    cudaGetSymbolAddress((void**)&pWp, g_Wproj);

    int smem = NSTG * ST_FL * sizeof(float);   // 98304 bytes dynamic (+12KB static)
    cudaFuncSetAttribute(gemm_mma_kernel<0>, cudaFuncAttributeMaxDynamicSharedMemorySize, smem);
    cudaFuncSetAttribute(gemm_mma_kernel<1>, cudaFuncAttributeMaxDynamicSharedMemorySize, smem);

    prep_kernel<<<1024, 256>>>(qkv_w, qkv_res, qkv_gate, proj_w, proj_res, proj_gate,
                               bias_table, rel_index);
    lora_down_kernel<0><<<M_TOK / 16, 256>>>(x, qkv_down, pT, pX);
    dim3 gq(QKV_NPACK / BNP, M_TOK / BM);   // (18, 784): n fastest -> A read once
    gemm_mma_kernel<0><<<gq, 256, smem>>>(pX, pWq, qkv_b, qkv_up, pT, nullptr);
    attn_kernel<<<2048 * NH, 128>>>(mask, pAO);
    lora_down_kernel<1><<<M_TOK / 16, 256>>>(pAO, proj_down, pT, nullptr);
    dim3 gp(PROJ_NPACK / BNP, M_TOK / BM);  // (6, 784)
    gemm_mma_kernel<1><<<gp, 256, smem>>>(pAO, pWp, proj_b, proj_up, pT, out);
}